// round 1
// baseline (speedup 1.0000x reference)
#include <cuda_runtime.h>

#define NN 100000
#define EE 1600000
#define ET 1700000   // EE + NN (self-loops appended)
#define INF 128
#define HC 64
#define NEG 0.2f

// ---------------- scratch (static __device__ globals; no allocation) ----------------
__device__ float4 g_h4[NN * 16];       // h: [N,64] fp32, viewed as 16 float4 per row
__device__ float4 g_asrc4[NN];         // a_src: [N,4]
__device__ float4 g_adst4[NN];         // a_dst: [N,4]
__device__ int    g_deg[NN];
__device__ int    g_rowptr[NN + 1];
__device__ int    g_cursor[NN];
__device__ int    g_col[ET];           // CSR column list: original edge ids, grouped by dst

// ---------------- kernel 1: h = x @ W, plus per-node attention dots ----------------
// One warp per row; W staged in smem once per block. Lane owns output cols (2l, 2l+1).
__global__ __launch_bounds__(256) void gemm_attn(
    const float* __restrict__ x, const float* __restrict__ W,
    const float* __restrict__ att_src, const float* __restrict__ att_dst)
{
    __shared__ float Ws[INF * HC];   // 32 KB
    int t = threadIdx.x;
    for (int i = t; i < INF * HC; i += blockDim.x) Ws[i] = W[i];
    __syncthreads();

    int lane = t & 31, w = t >> 5;
    int gw = blockIdx.x * (blockDim.x >> 5) + w;
    int nwarps = gridDim.x * (blockDim.x >> 5);

    float as0 = att_src[2 * lane], as1 = att_src[2 * lane + 1];
    float ad0 = att_dst[2 * lane], ad1 = att_dst[2 * lane + 1];
    const float2* Ws2 = (const float2*)Ws;

    for (int row = gw; row < NN; row += nwarps) {
        float4 xq = ((const float4*)x)[row * 32 + lane];   // lane owns k in [4l,4l+4)
        float acc0 = 0.f, acc1 = 0.f;
        #pragma unroll
        for (int kk = 0; kk < INF; kk += 4) {
            int sl = kk >> 2;
            float v0 = __shfl_sync(0xffffffffu, xq.x, sl);
            float v1 = __shfl_sync(0xffffffffu, xq.y, sl);
            float v2 = __shfl_sync(0xffffffffu, xq.z, sl);
            float v3 = __shfl_sync(0xffffffffu, xq.w, sl);
            float2 w0 = Ws2[(kk + 0) * 32 + lane];
            float2 w1 = Ws2[(kk + 1) * 32 + lane];
            float2 w2 = Ws2[(kk + 2) * 32 + lane];
            float2 w3 = Ws2[(kk + 3) * 32 + lane];
            acc0 = fmaf(v0, w0.x, acc0); acc1 = fmaf(v0, w0.y, acc1);
            acc0 = fmaf(v1, w1.x, acc0); acc1 = fmaf(v1, w1.y, acc1);
            acc0 = fmaf(v2, w2.x, acc0); acc1 = fmaf(v2, w2.y, acc1);
            acc0 = fmaf(v3, w3.x, acc0); acc1 = fmaf(v3, w3.y, acc1);
        }
        ((float2*)g_h4)[row * 32 + lane] = make_float2(acc0, acc1);

        // attention dots: reduce within each 8-lane (=16 col = 1 head) group
        float ps = acc0 * as0 + acc1 * as1;
        float pd = acc0 * ad0 + acc1 * ad1;
        #pragma unroll
        for (int off = 4; off > 0; off >>= 1) {
            ps += __shfl_xor_sync(0xffffffffu, ps, off);
            pd += __shfl_xor_sync(0xffffffffu, pd, off);
        }
        if ((lane & 7) == 0) {
            int hh = lane >> 3;
            float* asrc = (float*)g_asrc4;
            float* adst = (float*)g_adst4;
            asrc[row * 4 + hh] = ps;
            adst[row * 4 + hh] = pd;
        }
    }
}

// ---------------- CSR build ----------------
__global__ void zero_deg_kernel() {
    int i = blockIdx.x * blockDim.x + threadIdx.x;
    if (i < NN) g_deg[i] = 0;
}

__global__ void hist_kernel(const int* __restrict__ ei) {
    int i = blockIdx.x * blockDim.x + threadIdx.x;
    if (i < ET) {
        int d = (i < EE) ? ei[EE + i] : (i - EE);
        atomicAdd(&g_deg[d], 1);
    }
}

// single-block exclusive scan of g_deg -> g_rowptr (+ copy into g_cursor)
__global__ __launch_bounds__(1024) void scan_kernel() {
    __shared__ int sums[1024];
    const int CH = (NN + 1023) / 1024;   // 98
    int t = threadIdx.x;
    int beg = t * CH;
    int end = min(beg + CH, NN);
    int s = 0;
    for (int i = beg; i < end; i++) s += g_deg[i];
    sums[t] = s;
    __syncthreads();
    // Hillis-Steele inclusive scan
    for (int off = 1; off < 1024; off <<= 1) {
        int v = 0;
        if (t >= off) v = sums[t - off];
        __syncthreads();
        if (t >= off) sums[t] += v;
        __syncthreads();
    }
    int prefix = (t > 0) ? sums[t - 1] : 0;
    for (int i = beg; i < end; i++) {
        g_rowptr[i] = prefix;
        g_cursor[i] = prefix;
        prefix += g_deg[i];
    }
    if (t == 0) g_rowptr[NN] = sums[1023];
}

__global__ void scatter_kernel(const int* __restrict__ ei) {
    int i = blockIdx.x * blockDim.x + threadIdx.x;
    if (i < ET) {
        int d = (i < EE) ? ei[EE + i] : (i - EE);
        int p = atomicAdd(&g_cursor[d], 1);
        g_col[p] = i;
    }
}

// ---------------- kernel 2: per-dst softmax + aggregation (warp per dst) ----------------
__global__ __launch_bounds__(256) void aggregate_kernel(
    const int* __restrict__ ei, const float* __restrict__ bias,
    float* __restrict__ out, float* __restrict__ alpha_out)
{
    __shared__ float s_al[8][32][4];
    __shared__ int   s_src[8][32];

    int lane = threadIdx.x & 31, w = threadIdx.x >> 5;
    int d = blockIdx.x * 8 + w;
    if (d >= NN) return;

    int beg = g_rowptr[d];
    int end = g_rowptr[d + 1];
    float4 ad = g_adst4[d];

    // ---- pass 1: per-head max of leaky_relu(a_src[src] + a_dst[dst]) ----
    float m0 = -1e30f, m1 = -1e30f, m2 = -1e30f, m3 = -1e30f;
    for (int j = beg + lane; j < end; j += 32) {
        int eid = g_col[j];
        int s = (eid < EE) ? ei[eid] : (eid - EE);
        float4 as = g_asrc4[s];
        float e0 = as.x + ad.x; e0 = (e0 > 0.f) ? e0 : NEG * e0; m0 = fmaxf(m0, e0);
        float e1 = as.y + ad.y; e1 = (e1 > 0.f) ? e1 : NEG * e1; m1 = fmaxf(m1, e1);
        float e2 = as.z + ad.z; e2 = (e2 > 0.f) ? e2 : NEG * e2; m2 = fmaxf(m2, e2);
        float e3 = as.w + ad.w; e3 = (e3 > 0.f) ? e3 : NEG * e3; m3 = fmaxf(m3, e3);
    }
    #pragma unroll
    for (int off = 16; off > 0; off >>= 1) {
        m0 = fmaxf(m0, __shfl_xor_sync(0xffffffffu, m0, off));
        m1 = fmaxf(m1, __shfl_xor_sync(0xffffffffu, m1, off));
        m2 = fmaxf(m2, __shfl_xor_sync(0xffffffffu, m2, off));
        m3 = fmaxf(m3, __shfl_xor_sync(0xffffffffu, m3, off));
    }

    // ---- pass 2: sum of exp(e - max) ----
    float s0 = 0.f, s1 = 0.f, s2 = 0.f, s3 = 0.f;
    for (int j = beg + lane; j < end; j += 32) {
        int eid = g_col[j];
        int s = (eid < EE) ? ei[eid] : (eid - EE);
        float4 as = g_asrc4[s];
        float e0 = as.x + ad.x; e0 = (e0 > 0.f) ? e0 : NEG * e0; s0 += __expf(e0 - m0);
        float e1 = as.y + ad.y; e1 = (e1 > 0.f) ? e1 : NEG * e1; s1 += __expf(e1 - m1);
        float e2 = as.z + ad.z; e2 = (e2 > 0.f) ? e2 : NEG * e2; s2 += __expf(e2 - m2);
        float e3 = as.w + ad.w; e3 = (e3 > 0.f) ? e3 : NEG * e3; s3 += __expf(e3 - m3);
    }
    #pragma unroll
    for (int off = 16; off > 0; off >>= 1) {
        s0 += __shfl_xor_sync(0xffffffffu, s0, off);
        s1 += __shfl_xor_sync(0xffffffffu, s1, off);
        s2 += __shfl_xor_sync(0xffffffffu, s2, off);
        s3 += __shfl_xor_sync(0xffffffffu, s3, off);
    }
    float i0 = 1.f / (s0 + 1e-16f);
    float i1 = 1.f / (s1 + 1e-16f);
    float i2 = 1.f / (s2 + 1e-16f);
    float i3 = 1.f / (s3 + 1e-16f);

    // ---- pass 3: alpha write + weighted aggregation (lane owns cols 2l, 2l+1) ----
    float acc0 = 0.f, acc1 = 0.f;
    int myh = lane >> 3;   // head of column 2*lane
    for (int j0 = beg; j0 < end; j0 += 32) {
        int j = j0 + lane;
        int cnt = min(32, end - j0);
        if (j < end) {
            int eid = g_col[j];
            int s = (eid < EE) ? ei[eid] : (eid - EE);
            float4 as = g_asrc4[s];
            float e0 = as.x + ad.x; e0 = (e0 > 0.f) ? e0 : NEG * e0;
            float e1 = as.y + ad.y; e1 = (e1 > 0.f) ? e1 : NEG * e1;
            float e2 = as.z + ad.z; e2 = (e2 > 0.f) ? e2 : NEG * e2;
            float e3 = as.w + ad.w; e3 = (e3 > 0.f) ? e3 : NEG * e3;
            float a0 = __expf(e0 - m0) * i0;
            float a1 = __expf(e1 - m1) * i1;
            float a2 = __expf(e2 - m2) * i2;
            float a3 = __expf(e3 - m3) * i3;
            ((float4*)alpha_out)[eid] = make_float4(a0, a1, a2, a3);
            s_src[w][lane] = s;
            s_al[w][lane][0] = a0; s_al[w][lane][1] = a1;
            s_al[w][lane][2] = a2; s_al[w][lane][3] = a3;
        }
        __syncwarp();
        for (int k = 0; k < cnt; k++) {
            int sk = s_src[w][k];
            float al = s_al[w][k][myh];
            float2 hv = ((const float2*)g_h4)[sk * 32 + lane];
            acc0 = fmaf(al, hv.x, acc0);
            acc1 = fmaf(al, hv.y, acc1);
        }
        __syncwarp();
    }

    // epilogue: +bias, ELU
    float b0 = bias[2 * lane], b1 = bias[2 * lane + 1];
    float o0 = acc0 + b0, o1 = acc1 + b1;
    o0 = (o0 > 0.f) ? o0 : (__expf(o0) - 1.f);
    o1 = (o1 > 0.f) ? o1 : (__expf(o1) - 1.f);
    ((float2*)out)[d * 32 + lane] = make_float2(o0, o1);
}

// ---------------- launch ----------------
extern "C" void kernel_launch(void* const* d_in, const int* in_sizes, int n_in,
                              void* d_out, int out_size)
{
    const float* x       = (const float*)d_in[0];
    const int*   ei      = (const int*)  d_in[1];   // [2,E]: src = ei[0:E), dst = ei[E:2E)
    const float* W       = (const float*)d_in[2];
    const float* att_src = (const float*)d_in[3];
    const float* att_dst = (const float*)d_in[4];
    const float* bias    = (const float*)d_in[5];

    float* out   = (float*)d_out;                  // [N, 64]
    float* alpha = out + (size_t)NN * HC;          // [Etot, 4]

    gemm_attn<<<592, 256>>>(x, W, att_src, att_dst);
    zero_deg_kernel<<<(NN + 255) / 256, 256>>>();
    hist_kernel<<<(ET + 255) / 256, 256>>>(ei);
    scan_kernel<<<1, 1024>>>();
    scatter_kernel<<<(ET + 255) / 256, 256>>>(ei);
    aggregate_kernel<<<(NN + 7) / 8, 256>>>(ei, bias, out, alpha);
}

// round 2
// speedup vs baseline: 1.5543x; 1.5543x over previous
#include <cuda_runtime.h>

#define NN 100000
#define EE 1600000
#define ET 1700000   // EE + NN (self-loops appended)
#define INF 128
#define HC 64
#define NEG 0.2f

#define SCAN_BLK 98      // ceil(NN / 1024)

// ---------------- scratch (static __device__ globals; no allocation) ----------------
__device__ float4 g_h4[NN * 16];       // h: [N,64] fp32, viewed as 16 float4 per row
__device__ float4 g_asrc4[NN];         // a_src: [N,4]
__device__ float4 g_adst4[NN];         // a_dst: [N,4]
__device__ int    g_deg[NN];
__device__ int    g_rowptr[NN + 1];
__device__ int    g_cursor[NN];
__device__ int    g_col[ET];           // CSR column list: original edge ids, grouped by dst
__device__ int    g_bsum[128];         // per-block partial sums for the scan

// ---------------- kernel 1: h = x @ W, plus per-node attention dots ----------------
__global__ __launch_bounds__(256) void gemm_attn(
    const float* __restrict__ x, const float* __restrict__ W,
    const float* __restrict__ att_src, const float* __restrict__ att_dst)
{
    __shared__ float Ws[INF * HC];   // 32 KB
    int t = threadIdx.x;
    for (int i = t; i < INF * HC; i += blockDim.x) Ws[i] = W[i];
    __syncthreads();

    int lane = t & 31, w = t >> 5;
    int gw = blockIdx.x * (blockDim.x >> 5) + w;
    int nwarps = gridDim.x * (blockDim.x >> 5);

    float as0 = att_src[2 * lane], as1 = att_src[2 * lane + 1];
    float ad0 = att_dst[2 * lane], ad1 = att_dst[2 * lane + 1];
    const float2* Ws2 = (const float2*)Ws;

    for (int row = gw; row < NN; row += nwarps) {
        float4 xq = ((const float4*)x)[row * 32 + lane];   // lane owns k in [4l,4l+4)
        float acc0 = 0.f, acc1 = 0.f;
        #pragma unroll
        for (int kk = 0; kk < INF; kk += 4) {
            int sl = kk >> 2;
            float v0 = __shfl_sync(0xffffffffu, xq.x, sl);
            float v1 = __shfl_sync(0xffffffffu, xq.y, sl);
            float v2 = __shfl_sync(0xffffffffu, xq.z, sl);
            float v3 = __shfl_sync(0xffffffffu, xq.w, sl);
            float2 w0 = Ws2[(kk + 0) * 32 + lane];
            float2 w1 = Ws2[(kk + 1) * 32 + lane];
            float2 w2 = Ws2[(kk + 2) * 32 + lane];
            float2 w3 = Ws2[(kk + 3) * 32 + lane];
            acc0 = fmaf(v0, w0.x, acc0); acc1 = fmaf(v0, w0.y, acc1);
            acc0 = fmaf(v1, w1.x, acc0); acc1 = fmaf(v1, w1.y, acc1);
            acc0 = fmaf(v2, w2.x, acc0); acc1 = fmaf(v2, w2.y, acc1);
            acc0 = fmaf(v3, w3.x, acc0); acc1 = fmaf(v3, w3.y, acc1);
        }
        ((float2*)g_h4)[row * 32 + lane] = make_float2(acc0, acc1);

        float ps = acc0 * as0 + acc1 * as1;
        float pd = acc0 * ad0 + acc1 * ad1;
        #pragma unroll
        for (int off = 4; off > 0; off >>= 1) {
            ps += __shfl_xor_sync(0xffffffffu, ps, off);
            pd += __shfl_xor_sync(0xffffffffu, pd, off);
        }
        if ((lane & 7) == 0) {
            int hh = lane >> 3;
            ((float*)g_asrc4)[row * 4 + hh] = ps;
            ((float*)g_adst4)[row * 4 + hh] = pd;
        }
    }
}

// ---------------- CSR build ----------------
__global__ void zero_deg_kernel() {
    int i = blockIdx.x * blockDim.x + threadIdx.x;
    if (i < NN) g_deg[i] = 0;
}

__global__ void hist_kernel(const int* __restrict__ ei) {
    int i = blockIdx.x * blockDim.x + threadIdx.x;
    if (i < ET) {
        int d = (i < EE) ? ei[EE + i] : (i - EE);
        atomicAdd(&g_deg[d], 1);
    }
}

// --- 3-phase device-wide exclusive scan of g_deg -> g_rowptr / g_cursor ---
// phase 1: per-block (1024-element chunk) total
__global__ __launch_bounds__(256) void scan_p1() {
    __shared__ int sm[256];
    int t = threadIdx.x;
    int base = blockIdx.x * 1024 + t * 4;
    int s = 0;
    #pragma unroll
    for (int k = 0; k < 4; k++) { int i = base + k; if (i < NN) s += g_deg[i]; }
    sm[t] = s;
    __syncthreads();
    #pragma unroll
    for (int off = 128; off > 0; off >>= 1) {
        if (t < off) sm[t] += sm[t + off];
        __syncthreads();
    }
    if (t == 0) g_bsum[blockIdx.x] = sm[0];
}

// phase 2: exclusive scan of the 98 block sums (single tiny block)
__global__ __launch_bounds__(128) void scan_p2() {
    __shared__ int sm[128];
    int t = threadIdx.x;
    int v = (t < SCAN_BLK) ? g_bsum[t] : 0;
    sm[t] = v;
    __syncthreads();
    #pragma unroll
    for (int off = 1; off < 128; off <<= 1) {
        int u = (t >= off) ? sm[t - off] : 0;
        __syncthreads();
        sm[t] += u;
        __syncthreads();
    }
    if (t < SCAN_BLK) g_bsum[t] = sm[t] - v;      // exclusive
    if (t == 127) g_rowptr[NN] = sm[127];          // grand total
}

// phase 3: per-block scan with global offset; write rowptr + cursor
__global__ __launch_bounds__(256) void scan_p3() {
    __shared__ int sm[256];
    int t = threadIdx.x;
    int base = blockIdx.x * 1024 + t * 4;
    int d0 = 0, d1 = 0, d2 = 0, d3 = 0;
    if (base     < NN) d0 = g_deg[base];
    if (base + 1 < NN) d1 = g_deg[base + 1];
    if (base + 2 < NN) d2 = g_deg[base + 2];
    if (base + 3 < NN) d3 = g_deg[base + 3];
    int s = d0 + d1 + d2 + d3;
    sm[t] = s;
    __syncthreads();
    #pragma unroll
    for (int off = 1; off < 256; off <<= 1) {
        int u = (t >= off) ? sm[t - off] : 0;
        __syncthreads();
        sm[t] += u;
        __syncthreads();
    }
    int prefix = g_bsum[blockIdx.x] + sm[t] - s;   // exclusive prefix for this thread
    if (base < NN)     { g_rowptr[base]     = prefix; g_cursor[base]     = prefix; prefix += d0; }
    if (base + 1 < NN) { g_rowptr[base + 1] = prefix; g_cursor[base + 1] = prefix; prefix += d1; }
    if (base + 2 < NN) { g_rowptr[base + 2] = prefix; g_cursor[base + 2] = prefix; prefix += d2; }
    if (base + 3 < NN) { g_rowptr[base + 3] = prefix; g_cursor[base + 3] = prefix; }
}

__global__ void scatter_kernel(const int* __restrict__ ei) {
    int i = blockIdx.x * blockDim.x + threadIdx.x;
    if (i < ET) {
        int d = (i < EE) ? ei[EE + i] : (i - EE);
        int p = atomicAdd(&g_cursor[d], 1);
        g_col[p] = i;
    }
}

// ---------------- kernel 2: per-dst softmax + aggregation (warp per dst) ----------------
__global__ __launch_bounds__(256) void aggregate_kernel(
    const int* __restrict__ ei, const float* __restrict__ bias,
    float* __restrict__ out, float* __restrict__ alpha_out)
{
    __shared__ float s_al[8][32][4];
    __shared__ int   s_src[8][32];

    int lane = threadIdx.x & 31, w = threadIdx.x >> 5;
    int d = blockIdx.x * 8 + w;
    if (d >= NN) return;

    int beg = g_rowptr[d];
    int end = g_rowptr[d + 1];
    float4 ad = g_adst4[d];

    // ---- pass 1: per-head max of leaky_relu(a_src[src] + a_dst[dst]) ----
    float m0 = -1e30f, m1 = -1e30f, m2 = -1e30f, m3 = -1e30f;
    for (int j = beg + lane; j < end; j += 32) {
        int eid = g_col[j];
        int s = (eid < EE) ? ei[eid] : (eid - EE);
        float4 as = g_asrc4[s];
        float e0 = as.x + ad.x; e0 = (e0 > 0.f) ? e0 : NEG * e0; m0 = fmaxf(m0, e0);
        float e1 = as.y + ad.y; e1 = (e1 > 0.f) ? e1 : NEG * e1; m1 = fmaxf(m1, e1);
        float e2 = as.z + ad.z; e2 = (e2 > 0.f) ? e2 : NEG * e2; m2 = fmaxf(m2, e2);
        float e3 = as.w + ad.w; e3 = (e3 > 0.f) ? e3 : NEG * e3; m3 = fmaxf(m3, e3);
    }
    #pragma unroll
    for (int off = 16; off > 0; off >>= 1) {
        m0 = fmaxf(m0, __shfl_xor_sync(0xffffffffu, m0, off));
        m1 = fmaxf(m1, __shfl_xor_sync(0xffffffffu, m1, off));
        m2 = fmaxf(m2, __shfl_xor_sync(0xffffffffu, m2, off));
        m3 = fmaxf(m3, __shfl_xor_sync(0xffffffffu, m3, off));
    }

    // ---- pass 2: sum of exp(e - max) ----
    float s0 = 0.f, s1 = 0.f, s2 = 0.f, s3 = 0.f;
    for (int j = beg + lane; j < end; j += 32) {
        int eid = g_col[j];
        int s = (eid < EE) ? ei[eid] : (eid - EE);
        float4 as = g_asrc4[s];
        float e0 = as.x + ad.x; e0 = (e0 > 0.f) ? e0 : NEG * e0; s0 += __expf(e0 - m0);
        float e1 = as.y + ad.y; e1 = (e1 > 0.f) ? e1 : NEG * e1; s1 += __expf(e1 - m1);
        float e2 = as.z + ad.z; e2 = (e2 > 0.f) ? e2 : NEG * e2; s2 += __expf(e2 - m2);
        float e3 = as.w + ad.w; e3 = (e3 > 0.f) ? e3 : NEG * e3; s3 += __expf(e3 - m3);
    }
    #pragma unroll
    for (int off = 16; off > 0; off >>= 1) {
        s0 += __shfl_xor_sync(0xffffffffu, s0, off);
        s1 += __shfl_xor_sync(0xffffffffu, s1, off);
        s2 += __shfl_xor_sync(0xffffffffu, s2, off);
        s3 += __shfl_xor_sync(0xffffffffu, s3, off);
    }
    float i0 = 1.f / (s0 + 1e-16f);
    float i1 = 1.f / (s1 + 1e-16f);
    float i2 = 1.f / (s2 + 1e-16f);
    float i3 = 1.f / (s3 + 1e-16f);

    // ---- pass 3: alpha write + weighted aggregation (lane owns cols 2l, 2l+1) ----
    float acc0 = 0.f, acc1 = 0.f;
    int myh = lane >> 3;   // head of column 2*lane
    for (int j0 = beg; j0 < end; j0 += 32) {
        int j = j0 + lane;
        int cnt = min(32, end - j0);
        if (j < end) {
            int eid = g_col[j];
            int s = (eid < EE) ? ei[eid] : (eid - EE);
            float4 as = g_asrc4[s];
            float e0 = as.x + ad.x; e0 = (e0 > 0.f) ? e0 : NEG * e0;
            float e1 = as.y + ad.y; e1 = (e1 > 0.f) ? e1 : NEG * e1;
            float e2 = as.z + ad.z; e2 = (e2 > 0.f) ? e2 : NEG * e2;
            float e3 = as.w + ad.w; e3 = (e3 > 0.f) ? e3 : NEG * e3;
            float a0 = __expf(e0 - m0) * i0;
            float a1 = __expf(e1 - m1) * i1;
            float a2 = __expf(e2 - m2) * i2;
            float a3 = __expf(e3 - m3) * i3;
            ((float4*)alpha_out)[eid] = make_float4(a0, a1, a2, a3);
            s_src[w][lane] = s;
            s_al[w][lane][0] = a0; s_al[w][lane][1] = a1;
            s_al[w][lane][2] = a2; s_al[w][lane][3] = a3;
        }
        __syncwarp();
        for (int k = 0; k < cnt; k++) {
            int sk = s_src[w][k];
            float al = s_al[w][k][myh];
            float2 hv = ((const float2*)g_h4)[sk * 32 + lane];
            acc0 = fmaf(al, hv.x, acc0);
            acc1 = fmaf(al, hv.y, acc1);
        }
        __syncwarp();
    }

    // epilogue: +bias, ELU
    float b0 = bias[2 * lane], b1 = bias[2 * lane + 1];
    float o0 = acc0 + b0, o1 = acc1 + b1;
    o0 = (o0 > 0.f) ? o0 : (__expf(o0) - 1.f);
    o1 = (o1 > 0.f) ? o1 : (__expf(o1) - 1.f);
    ((float2*)out)[d * 32 + lane] = make_float2(o0, o1);
}

// ---------------- launch ----------------
extern "C" void kernel_launch(void* const* d_in, const int* in_sizes, int n_in,
                              void* d_out, int out_size)
{
    const float* x       = (const float*)d_in[0];
    const int*   ei      = (const int*)  d_in[1];   // [2,E]: src = ei[0:E), dst = ei[E:2E)
    const float* W       = (const float*)d_in[2];
    const float* att_src = (const float*)d_in[3];
    const float* att_dst = (const float*)d_in[4];
    const float* bias    = (const float*)d_in[5];

    float* out   = (float*)d_out;                  // [N, 64]
    float* alpha = out + (size_t)NN * HC;          // [Etot, 4]

    gemm_attn<<<592, 256>>>(x, W, att_src, att_dst);
    zero_deg_kernel<<<(NN + 255) / 256, 256>>>();
    hist_kernel<<<(ET + 255) / 256, 256>>>(ei);
    scan_p1<<<SCAN_BLK, 256>>>();
    scan_p2<<<1, 128>>>();
    scan_p3<<<SCAN_BLK, 256>>>();
    scatter_kernel<<<(ET + 255) / 256, 256>>>(ei);
    aggregate_kernel<<<(NN + 7) / 8, 256>>>(ei, bias, out, alpha);
}